// round 1
// baseline (speedup 1.0000x reference)
#include <cuda_runtime.h>

// LSTM_8615704395881: B=64, T=16384, I=1, H=32, O=1.
// Persistent kernel: 1 CTA per batch element, 160 threads (5 warps).
//   warps 0-3: gate j = tid (order i,f,g,o), 32-MAC recurrent dot
//   warp 0   : cell/hidden update (lane k owns c_k)
//   warp 4   : linear head + residual for step t-1 (off critical path)

#define BATCH    64
#define TLEN     16384
#define HID      32
#define NTHREADS 160

__device__ __forceinline__ float fast_sigmoid(float x) {
    return __fdividef(1.0f, 1.0f + __expf(-x));
}
__device__ __forceinline__ float fast_tanh(float x) {
    return __fdividef(2.0f, 1.0f + __expf(-2.0f * x)) - 1.0f;
}

__global__ __launch_bounds__(NTHREADS, 1)
void lstm_persistent(const float* __restrict__ x,
                     const float* __restrict__ W_ih,
                     const float* __restrict__ W_hh,
                     const float* __restrict__ b_ih,
                     const float* __restrict__ b_hh,
                     const float* __restrict__ W_lin,
                     const float* __restrict__ b_lin,
                     float* __restrict__ out)
{
    __shared__ __align__(16) float h_s[2][HID];   // double-buffered hidden state
    __shared__ float g_s[4 * HID];                // activated gates (i,f,g,o)
    __shared__ float x_s[128];                    // staged input chunk

    const int tid  = threadIdx.x;
    const int wid  = tid >> 5;
    const int lane = tid & 31;
    const int b    = blockIdx.x;

    const float* xb = x   + (size_t)b * TLEN;
    float*       ob = out + (size_t)b * TLEN;

    // per-thread constants
    float w[HID];            // W_hh row (gate threads)
    float wih = 0.f, bsum = 0.f;
    float wl  = 0.f, bl   = 0.f;
    float c   = 0.f;         // cell state (warp 0 lanes)

    if (wid < 4) {
        #pragma unroll
        for (int m = 0; m < HID; m++) w[m] = W_hh[tid * HID + m];
        wih  = W_ih[tid];
        bsum = b_ih[tid] + b_hh[tid];
    } else {
        wl = W_lin[lane];
        bl = b_lin[0];
    }
    if (tid < HID) { h_s[0][tid] = 0.f; h_s[1][tid] = 0.f; }
    __syncthreads();

    for (int t = 0; t < TLEN; t++) {
        if ((t & 127) == 0) {                       // refill x chunk
            if (tid < 128) x_s[tid] = xb[t + tid];
            __syncthreads();
        }
        const float* hprev = h_s[t & 1];            // h_{t-1}

        if (wid < 4) {
            // gate pre-activation: x_t*W_ih[j] + (b_ih+b_hh)[j] + h_{t-1}.W_hh[j,:]
            float pre = fmaf(x_s[t & 127], wih, bsum);
            #pragma unroll
            for (int m4 = 0; m4 < 8; m4++) {
                float4 hv = *(const float4*)(hprev + 4 * m4);
                pre = fmaf(w[4*m4+0], hv.x, pre);
                pre = fmaf(w[4*m4+1], hv.y, pre);
                pre = fmaf(w[4*m4+2], hv.z, pre);
                pre = fmaf(w[4*m4+3], hv.w, pre);
            }
            g_s[tid] = (wid == 2) ? fast_tanh(pre) : fast_sigmoid(pre);
        } else if (t > 0) {
            // warp 4: out[t-1] = x[t-1] + b_lin + <h_{t-1}, W_lin>
            float p = hprev[lane] * wl;
            #pragma unroll
            for (int off = 16; off > 0; off >>= 1)
                p += __shfl_xor_sync(0xffffffffu, p, off);
            if (lane == 0) ob[t - 1] = xb[t - 1] + bl + p;
        }
        __syncthreads();                            // gates ready

        if (tid < HID) {                            // warp 0: cell update
            float gi = g_s[tid];
            float gf = g_s[HID     + tid];
            float gg = g_s[2 * HID + tid];
            float go = g_s[3 * HID + tid];
            c = fmaf(gf, c, gi * gg);
            h_s[(t + 1) & 1][tid] = go * fast_tanh(c);
        }
        __syncthreads();                            // h_t ready
    }

    // final output: h_{T-1} lives in buf[TLEN & 1] == buf[0]
    if (wid == 4) {
        float p = h_s[TLEN & 1][lane] * wl;
        #pragma unroll
        for (int off = 16; off > 0; off >>= 1)
            p += __shfl_xor_sync(0xffffffffu, p, off);
        if (lane == 0) ob[TLEN - 1] = xb[TLEN - 1] + bl + p;
    }
}

extern "C" void kernel_launch(void* const* d_in, const int* in_sizes, int n_in,
                              void* d_out, int out_size) {
    lstm_persistent<<<BATCH, NTHREADS>>>(
        (const float*)d_in[0],   // x
        (const float*)d_in[1],   // W_ih
        (const float*)d_in[2],   // W_hh
        (const float*)d_in[3],   // b_ih
        (const float*)d_in[4],   // b_hh
        (const float*)d_in[5],   // W_lin
        (const float*)d_in[6],   // b_lin
        (float*)d_out);
}

// round 2
// speedup vs baseline: 1.8621x; 1.8621x over previous
#include <cuda_runtime.h>

// LSTM_8615704395881: B=64, T=16384, I=1, H=32, O=1.
// 1 CTA / batch element, 160 threads.
//   warps 0-3: lane = 4*j_local + gate; warp w owns hidden units [8w, 8w+8).
//              Each lane: 32-MAC dot (f32x2 packed, 4 chains), MUFU.TANH
//              activation, in-warp gather of i,f,g,o via indexed shuffles,
//              redundant cell update, store h to SMEM ring. ONE barrier/step.
//   warp 4  : transposed linear head; lane l owns out[base+l], accumulates
//             one FMA term per step from the h ring. Off critical path.

#define BATCH    64
#define TLEN     16384
#define HID      32
#define NTHREADS 160
#define RING     64
#define RPAD     36   // floats per ring row (16B-aligned, avoids bad conflicts)

typedef unsigned long long ull;

__device__ __forceinline__ float tanh_fast(float x) {
    float r; asm("tanh.approx.f32 %0, %1;" : "=f"(r) : "f"(x)); return r;
}
__device__ __forceinline__ ull fma2(ull a, ull b, ull c) {
    ull d; asm("fma.rn.f32x2 %0, %1, %2, %3;" : "=l"(d) : "l"(a), "l"(b), "l"(c));
    return d;
}
__device__ __forceinline__ ull add2(ull a, ull b) {
    ull d; asm("add.rn.f32x2 %0, %1, %2;" : "=l"(d) : "l"(a), "l"(b));
    return d;
}
__device__ __forceinline__ ull pack2(float x, float y) {
    ull v; asm("mov.b64 %0, {%1, %2};" : "=l"(v) : "f"(x), "f"(y)); return v;
}
__device__ __forceinline__ float2 unpack2(ull v) {
    float2 f; asm("mov.b64 {%0, %1}, %2;" : "=f"(f.x), "=f"(f.y) : "l"(v)); return f;
}

__global__ __launch_bounds__(NTHREADS, 1)
void lstm_persistent(const float* __restrict__ x,
                     const float* __restrict__ W_ih,
                     const float* __restrict__ W_hh,
                     const float* __restrict__ b_ih,
                     const float* __restrict__ b_hh,
                     const float* __restrict__ W_lin,
                     const float* __restrict__ b_lin,
                     float* __restrict__ out)
{
    __shared__ __align__(16) float h_ring[RING][RPAD];
    __shared__ float wl_s[HID];

    const int tid  = threadIdx.x;
    const int wid  = tid >> 5;
    const int lane = tid & 31;
    const int b    = blockIdx.x;

    const float* xb = x   + (size_t)b * TLEN;
    float*       ob = out + (size_t)b * TLEN;

    if (tid < HID) { h_ring[RING - 1][tid] = 0.f; wl_s[tid] = W_lin[tid]; }
    __syncthreads();

    if (wid < 4) {
        const int g   = lane & 3;                 // gate: 0=i 1=f 2=g 3=o
        const int j   = (wid << 3) + (lane >> 2); // hidden unit
        const int row = (g << 5) + j;             // W_hh / bias row

        ull w2[16];
        #pragma unroll
        for (int k = 0; k < 16; k++)
            w2[k] = ((const ull*)(W_hh + row * HID))[k];

        const float wih  = W_ih[row];
        const float bsum = b_ih[row] + b_hh[row];
        // activation: res = tanh(pre * sarg) * sa + sb
        // gate 2 (tanh): sarg=1, sa=1, sb=0 ; others (sigmoid): 0.5, 0.5, 0.5
        const float sarg = (g == 2) ? 1.0f : 0.5f;
        const float sa   = (g == 2) ? 1.0f : 0.5f;
        const float sb   = (g == 2) ? 0.0f : 0.5f;
        const int base4  = lane & ~3;

        float c  = 0.f;
        float xc = xb[0];

        for (int t = 0; t < TLEN; t++) {
            // prefetch next x (consumed next iteration)
            int tn = t + 1 < TLEN ? t + 1 : TLEN - 1;
            float xn = __ldg(xb + tn);

            const float* hr = h_ring[(t + RING - 1) & (RING - 1)];

            ull acc0 = pack2(fmaf(xc, wih, bsum), 0.f);
            ull acc1 = 0ull, acc2 = 0ull, acc3 = 0ull;
            #pragma unroll
            for (int i = 0; i < 4; i++) {
                ulonglong2 ha = *(const ulonglong2*)(hr + 8 * i);
                ulonglong2 hb = *(const ulonglong2*)(hr + 8 * i + 4);
                acc0 = fma2(w2[4 * i + 0], ha.x, acc0);
                acc1 = fma2(w2[4 * i + 1], ha.y, acc1);
                acc2 = fma2(w2[4 * i + 2], hb.x, acc2);
                acc3 = fma2(w2[4 * i + 3], hb.y, acc3);
            }
            ull s = add2(add2(acc0, acc1), add2(acc2, acc3));
            float2 sf = unpack2(s);
            float pre = sf.x + sf.y;

            float act = fmaf(tanh_fast(pre * sarg), sa, sb);

            float iv = __shfl_sync(0xffffffffu, act, base4);
            float fv = __shfl_sync(0xffffffffu, act, base4 + 1);
            float gv = __shfl_sync(0xffffffffu, act, base4 + 2);
            float ov = __shfl_sync(0xffffffffu, act, base4 + 3);

            c = fmaf(fv, c, iv * gv);              // redundant across 4 lanes
            float h = ov * tanh_fast(c);
            h_ring[t & (RING - 1)][j] = h;         // same value, same addr x4

            xc = xn;
            __syncthreads();
        }
    } else {
        // warp 4: linear head, one term per step, one window (32 outs) behind
        const float bl = b_lin[0];
        float acc = 0.f, xpre = 0.f;
        int baserow = 0;

        for (int t = 0; t < TLEN; t++) {
            if (t >= 32) {
                int k = t & 31;
                if (k == 0) {
                    baserow = t - 32;
                    acc = 0.f;
                    xpre = __ldg(xb + baserow + lane);
                }
                float hv = h_ring[(baserow + lane) & (RING - 1)][k];
                acc = fmaf(hv, wl_s[k], acc);
                if (k == 31) ob[baserow + lane] = xpre + bl + acc;
            }
            __syncthreads();
        }
        // epilogue: last window [TLEN-32, TLEN)
        int base = TLEN - 32;
        float a = 0.f;
        #pragma unroll
        for (int k = 0; k < 32; k++)
            a = fmaf(h_ring[(base + lane) & (RING - 1)][k], wl_s[k], a);
        ob[base + lane] = __ldg(xb + base + lane) + bl + a;
    }
}

extern "C" void kernel_launch(void* const* d_in, const int* in_sizes, int n_in,
                              void* d_out, int out_size) {
    lstm_persistent<<<BATCH, NTHREADS>>>(
        (const float*)d_in[0],   // x
        (const float*)d_in[1],   // W_ih
        (const float*)d_in[2],   // W_hh
        (const float*)d_in[3],   // b_ih
        (const float*)d_in[4],   // b_hh
        (const float*)d_in[5],   // W_lin
        (const float*)d_in[6],   // b_lin
        (float*)d_out);
}

// round 3
// speedup vs baseline: 1.9315x; 1.0373x over previous
#include <cuda_runtime.h>

// LSTM_8615704395881: B=64, T=16384, I=1, H=32, O=1.
// Kernel 1 (recurrent): 1 CTA/batch, 128 threads (4 homogeneous warps).
//   lane = 4*j_local + gate ; warp w owns hidden units [8w, 8w+8).
//   Per step: 32-MAC dot (f32x2, 4 chains) -> MUFU.TANH activation
//   (0.5 scale pre-folded into weights for sigmoid gates) -> 4 indexed
//   shuffles gather i,f,g,o -> redundant cell update -> h to SMEM
//   (1 lane/unit) + h to global scratch. ONE 4-warp barrier per step.
// Kernel 2 (head): out = x + h_dev @ W_lin + b_lin, one thread per (b,t).

#define BATCH 64
#define TLEN  16384
#define HID   32
#define NT    128

typedef unsigned long long ull;

__device__ __align__(16) float h_dev[(size_t)BATCH * TLEN * HID];  // 128 MB scratch

__device__ __forceinline__ float tanh_fast(float x) {
    float r; asm("tanh.approx.f32 %0, %1;" : "=f"(r) : "f"(x)); return r;
}
__device__ __forceinline__ ull fma2(ull a, ull b, ull c) {
    ull d; asm("fma.rn.f32x2 %0, %1, %2, %3;" : "=l"(d) : "l"(a), "l"(b), "l"(c));
    return d;
}
__device__ __forceinline__ ull add2(ull a, ull b) {
    ull d; asm("add.rn.f32x2 %0, %1, %2;" : "=l"(d) : "l"(a), "l"(b));
    return d;
}
__device__ __forceinline__ ull pack2(float x, float y) {
    ull v; asm("mov.b64 %0, {%1, %2};" : "=l"(v) : "f"(x), "f"(y)); return v;
}
__device__ __forceinline__ float2 unpack2(ull v) {
    float2 f; asm("mov.b64 {%0, %1}, %2;" : "=f"(f.x), "=f"(f.y) : "l"(v)); return f;
}

// one LSTM timestep (compile-time ping-pong buffers)
#define STEP(XC, HR, HW)                                                      \
    do {                                                                      \
        ull a0 = pack2(fmaf((XC), wih, bsum), 0.f);                           \
        ull a1 = 0ull, a2 = 0ull, a3 = 0ull;                                  \
        _Pragma("unroll")                                                     \
        for (int i = 0; i < 4; i++) {                                         \
            ulonglong2 ha = *(const ulonglong2*)((HR) + 8 * i);               \
            ulonglong2 hb2 = *(const ulonglong2*)((HR) + 8 * i + 4);          \
            a0 = fma2(w2[4 * i + 0], ha.x, a0);                               \
            a1 = fma2(w2[4 * i + 1], ha.y, a1);                               \
            a2 = fma2(w2[4 * i + 2], hb2.x, a2);                              \
            a3 = fma2(w2[4 * i + 3], hb2.y, a3);                              \
        }                                                                     \
        ull s = add2(add2(a0, a1), add2(a2, a3));                             \
        float2 sf = unpack2(s);                                               \
        float act = fmaf(tanh_fast(sf.x + sf.y), sa, sb);                     \
        float iv = __shfl_sync(0xffffffffu, act, base4);                      \
        float fv = __shfl_sync(0xffffffffu, act, base4 + 1);                  \
        float gv = __shfl_sync(0xffffffffu, act, base4 + 2);                  \
        float ov = __shfl_sync(0xffffffffu, act, base4 + 3);                  \
        c = fmaf(fv, c, iv * gv);                                             \
        float hres = ov * tanh_fast(c);                                       \
        if (writer) { (HW)[j] = hres; *gout = hres; }                         \
        gout += HID;                                                          \
        __syncthreads();                                                      \
    } while (0)

__global__ __launch_bounds__(NT, 1)
void lstm_rec(const float* __restrict__ x,
              const float* __restrict__ W_ih,
              const float* __restrict__ W_hh,
              const float* __restrict__ b_ih,
              const float* __restrict__ b_hh)
{
    __shared__ __align__(16) float hb[2][HID];

    const int tid  = threadIdx.x;
    const int wid  = tid >> 5;
    const int lane = tid & 31;
    const int b    = blockIdx.x;

    const int g   = lane & 3;                  // gate: 0=i 1=f 2=g 3=o
    const int j   = (wid << 3) + (lane >> 2);  // hidden unit
    const int row = (g << 5) + j;

    // sigmoid(z) = 0.5*tanh(z/2)+0.5 : fold the /2 into the weights
    const float scale = (g == 2) ? 1.0f : 0.5f;
    const float sa    = (g == 2) ? 1.0f : 0.5f;
    const float sb    = (g == 2) ? 0.0f : 0.5f;

    ull w2[16];
    #pragma unroll
    for (int k = 0; k < 16; k++) {
        float wa = W_hh[row * HID + 2 * k]     * scale;
        float wb = W_hh[row * HID + 2 * k + 1] * scale;
        w2[k] = pack2(wa, wb);
    }
    const float wih  = W_ih[row] * scale;
    const float bsum = (b_ih[row] + b_hh[row]) * scale;
    const int base4  = lane & ~3;
    const bool writer = (g == 0);

    float* gout = h_dev + (size_t)b * TLEN * HID + j;
    const float* xb = x + (size_t)b * TLEN;
    float c = 0.f;

    if (tid < HID) hb[0][tid] = 0.f;
    __syncthreads();

    for (int t = 0; t < TLEN; t += 4) {
        float4 xq = *(const float4*)(xb + t);
        STEP(xq.x, hb[0], hb[1]);
        STEP(xq.y, hb[1], hb[0]);
        STEP(xq.z, hb[0], hb[1]);
        STEP(xq.w, hb[1], hb[0]);
    }
}

__global__ __launch_bounds__(256, 4)
void lin_head(const float* __restrict__ x,
              const float* __restrict__ W_lin,
              const float* __restrict__ b_lin,
              float* __restrict__ out)
{
    const int idx = blockIdx.x * 256 + threadIdx.x;   // b*TLEN + t
    const float4* hp = (const float4*)(h_dev + (size_t)idx * HID);

    float a0 = 0.f, a1 = 0.f, a2 = 0.f, a3 = 0.f;
    #pragma unroll
    for (int q = 0; q < 8; q += 4) {
        float4 h0 = hp[q],     w0 = __ldg((const float4*)W_lin + q);
        float4 h1 = hp[q + 1], w1 = __ldg((const float4*)W_lin + q + 1);
        float4 h2 = hp[q + 2], w2 = __ldg((const float4*)W_lin + q + 2);
        float4 h3 = hp[q + 3], w3 = __ldg((const float4*)W_lin + q + 3);
        a0 = fmaf(h0.x, w0.x, fmaf(h0.y, w0.y, fmaf(h0.z, w0.z, fmaf(h0.w, w0.w, a0))));
        a1 = fmaf(h1.x, w1.x, fmaf(h1.y, w1.y, fmaf(h1.z, w1.z, fmaf(h1.w, w1.w, a1))));
        a2 = fmaf(h2.x, w2.x, fmaf(h2.y, w2.y, fmaf(h2.z, w2.z, fmaf(h2.w, w2.w, a2))));
        a3 = fmaf(h3.x, w3.x, fmaf(h3.y, w3.y, fmaf(h3.z, w3.z, fmaf(h3.w, w3.w, a3))));
    }
    out[idx] = x[idx] + __ldg(b_lin) + ((a0 + a1) + (a2 + a3));
}

extern "C" void kernel_launch(void* const* d_in, const int* in_sizes, int n_in,
                              void* d_out, int out_size) {
    lstm_rec<<<BATCH, NT>>>(
        (const float*)d_in[0],   // x
        (const float*)d_in[1],   // W_ih
        (const float*)d_in[2],   // W_hh
        (const float*)d_in[3],   // b_ih
        (const float*)d_in[4]);  // b_hh
    lin_head<<<(BATCH * TLEN) / 256, 256>>>(
        (const float*)d_in[0],   // x
        (const float*)d_in[5],   // W_lin
        (const float*)d_in[6],   // b_lin
        (float*)d_out);
}

// round 4
// speedup vs baseline: 2.1562x; 1.1163x over previous
#include <cuda_runtime.h>
#include <cuda_fp16.h>

// LSTM_8615704395881: B=64, T=16384, I=1, H=32, O=1.
// Kernel 1 (recurrent): 1 CTA/batch, 128 threads (4 homogeneous warps).
//   lane = 4*j_local + gate ; warp w owns hidden units [8w, 8w+8).
//   Per step: 32-MAC dot (f32x2, 4 chains) -> MUFU.TANH activation
//   (0.5 folded into weights for sigmoid gates) -> 4 indexed shuffles
//   gather i,f,g,o -> redundant cell update -> h to SMEM (writer lane)
//   + fp16 h to global scratch (off-path). ONE 4-warp barrier per step.
//   x prefetched one 4-step block ahead (register double buffer).
// Kernel 2 (head): out = x + h_dev @ W_lin + b_lin, 1 thread per (b,t).

#define BATCH 64
#define TLEN  16384
#define HID   32
#define NT    128

typedef unsigned long long ull;

__device__ __align__(16) __half h_dev[(size_t)BATCH * TLEN * HID];  // 64 MB fp16 scratch

__device__ __forceinline__ float tanh_fast(float x) {
    float r; asm("tanh.approx.f32 %0, %1;" : "=f"(r) : "f"(x)); return r;
}
__device__ __forceinline__ ull fma2(ull a, ull b, ull c) {
    ull d; asm("fma.rn.f32x2 %0, %1, %2, %3;" : "=l"(d) : "l"(a), "l"(b), "l"(c));
    return d;
}
__device__ __forceinline__ ull add2(ull a, ull b) {
    ull d; asm("add.rn.f32x2 %0, %1, %2;" : "=l"(d) : "l"(a), "l"(b));
    return d;
}
__device__ __forceinline__ ull pack2(float x, float y) {
    ull v; asm("mov.b64 %0, {%1, %2};" : "=l"(v) : "f"(x), "f"(y)); return v;
}
__device__ __forceinline__ float2 unpack2(ull v) {
    float2 f; asm("mov.b64 {%0, %1}, %2;" : "=f"(f.x), "=f"(f.y) : "l"(v)); return f;
}

// one LSTM timestep (compile-time ping-pong buffers)
#define STEP(XC, HR, HW)                                                      \
    do {                                                                      \
        ull a0 = pack2(fmaf((XC), wih, bsum), 0.f);                           \
        ull a1 = 0ull, a2 = 0ull, a3 = 0ull;                                  \
        _Pragma("unroll")                                                     \
        for (int i = 0; i < 4; i++) {                                         \
            ulonglong2 ha  = *(const ulonglong2*)((HR) + 8 * i);              \
            ulonglong2 hb2 = *(const ulonglong2*)((HR) + 8 * i + 4);          \
            a0 = fma2(w2[4 * i + 0], ha.x,  a0);                              \
            a1 = fma2(w2[4 * i + 1], ha.y,  a1);                              \
            a2 = fma2(w2[4 * i + 2], hb2.x, a2);                              \
            a3 = fma2(w2[4 * i + 3], hb2.y, a3);                              \
        }                                                                     \
        ull s = add2(add2(a0, a1), add2(a2, a3));                             \
        float2 sf = unpack2(s);                                               \
        float act = fmaf(tanh_fast(sf.x + sf.y), sa, sb);                     \
        float iv = __shfl_sync(0xffffffffu, act, base4);                      \
        float fv = __shfl_sync(0xffffffffu, act, base4 + 1);                  \
        float gv = __shfl_sync(0xffffffffu, act, base4 + 2);                  \
        float ov = __shfl_sync(0xffffffffu, act, base4 + 3);                  \
        c = fmaf(fv, c, iv * gv);                                             \
        float hres = ov * tanh_fast(c);                                       \
        if (writer) { (HW)[j] = hres; *gout = __float2half_rn(hres); }        \
        gout += HID;                                                          \
        __syncthreads();                                                      \
    } while (0)

__global__ __launch_bounds__(NT, 1)
void lstm_rec(const float* __restrict__ x,
              const float* __restrict__ W_ih,
              const float* __restrict__ W_hh,
              const float* __restrict__ b_ih,
              const float* __restrict__ b_hh)
{
    __shared__ __align__(16) float hb[2][HID];

    const int tid  = threadIdx.x;
    const int wid  = tid >> 5;
    const int lane = tid & 31;
    const int b    = blockIdx.x;

    const int g   = lane & 3;                  // gate: 0=i 1=f 2=g 3=o
    const int j   = (wid << 3) + (lane >> 2);  // hidden unit
    const int row = (g << 5) + j;

    // sigmoid(z) = 0.5*tanh(z/2)+0.5 : fold the /2 into the weights
    const float scale = (g == 2) ? 1.0f : 0.5f;
    const float sa    = (g == 2) ? 1.0f : 0.5f;
    const float sb    = (g == 2) ? 0.0f : 0.5f;

    ull w2[16];
    #pragma unroll
    for (int k = 0; k < 16; k++) {
        float wa = W_hh[row * HID + 2 * k]     * scale;
        float wb = W_hh[row * HID + 2 * k + 1] * scale;
        w2[k] = pack2(wa, wb);
    }
    const float wih  = W_ih[row] * scale;
    const float bsum = (b_ih[row] + b_hh[row]) * scale;
    const int base4  = lane & ~3;
    const bool writer = (g == 0);

    __half* gout = h_dev + (size_t)b * TLEN * HID + j;
    const float* xb = x + (size_t)b * TLEN;
    float c = 0.f;

    if (tid < HID) hb[0][tid] = 0.f;
    __syncthreads();

    // register double-buffered x prefetch: block t's data loaded at block t-4
    float4 xn = __ldg((const float4*)xb);
    for (int t = 0; t < TLEN; t += 4) {
        float4 xq = xn;
        int tn = (t + 4 < TLEN) ? (t + 4) : t;          // clamp tail (L1 hit)
        xn = __ldg((const float4*)(xb + tn));
        STEP(xq.x, hb[0], hb[1]);
        STEP(xq.y, hb[1], hb[0]);
        STEP(xq.z, hb[0], hb[1]);
        STEP(xq.w, hb[1], hb[0]);
    }
}

__global__ __launch_bounds__(256, 4)
void lin_head(const float* __restrict__ x,
              const float* __restrict__ W_lin,
              const float* __restrict__ b_lin,
              float* __restrict__ out)
{
    const int idx = blockIdx.x * 256 + threadIdx.x;   // b*TLEN + t
    const uint4* hp = (const uint4*)(h_dev + (size_t)idx * HID);  // 32 halves = 4x uint4

    float acc[4] = {0.f, 0.f, 0.f, 0.f};
    #pragma unroll
    for (int q = 0; q < 4; q++) {
        uint4 u = hp[q];                               // 8 halves
        const float4 wA = __ldg((const float4*)W_lin + 2 * q);
        const float4 wB = __ldg((const float4*)W_lin + 2 * q + 1);
        float2 f0 = __half22float2(*(const __half2*)&u.x);
        float2 f1 = __half22float2(*(const __half2*)&u.y);
        float2 f2 = __half22float2(*(const __half2*)&u.z);
        float2 f3 = __half22float2(*(const __half2*)&u.w);
        float a = fmaf(f0.x, wA.x, fmaf(f0.y, wA.y, 0.f));
        a = fmaf(f1.x, wA.z, fmaf(f1.y, wA.w, a));
        a = fmaf(f2.x, wB.x, fmaf(f2.y, wB.y, a));
        a = fmaf(f3.x, wB.z, fmaf(f3.y, wB.w, a));
        acc[q] = a;
    }
    out[idx] = x[idx] + __ldg(b_lin) + ((acc[0] + acc[1]) + (acc[2] + acc[3]));
}

extern "C" void kernel_launch(void* const* d_in, const int* in_sizes, int n_in,
                              void* d_out, int out_size) {
    lstm_rec<<<BATCH, NT>>>(
        (const float*)d_in[0],   // x
        (const float*)d_in[1],   // W_ih
        (const float*)d_in[2],   // W_hh
        (const float*)d_in[3],   // b_ih
        (const float*)d_in[4]);  // b_hh
    lin_head<<<(BATCH * TLEN) / 256, 256>>>(
        (const float*)d_in[0],   // x
        (const float*)d_in[5],   // W_lin
        (const float*)d_in[6],   // b_lin
        (float*)d_out);
}

// round 5
// speedup vs baseline: 2.1889x; 1.0152x over previous
#include <cuda_runtime.h>
#include <cuda_fp16.h>

// LSTM_8615704395881: B=64, T=16384, I=1, H=32, O=1.
// Kernel 1 (recurrent): 1 CTA/batch, 128 threads (4 homogeneous warps).
//   lane = 4*j_local + gate ; warp w owns hidden units [8w, 8w+8).
//   Per step: 32-MAC dot (f32x2, 4 chains) -> MUFU.TANH activation
//   (0.5 folded into weights for sigmoid gates) -> 3 indexed shuffles
//   gather i,f,g (writer lane g==3 owns o natively) -> redundant cell
//   update -> h STS (writer) -> barrier; fp16 h STG + bookkeeping after
//   the barrier (DEFER_BLOCKING window). x prefetched one block ahead.
// Kernel 2 (head): SMEM-staged coalesced read of fp16 h scratch;
//   out = x + h @ W_lin + b_lin.

#define BATCH 64
#define TLEN  16384
#define HID   32
#define NT    128

typedef unsigned long long ull;
typedef unsigned int uint;

__device__ __align__(16) __half h_dev[(size_t)BATCH * TLEN * HID];  // 64 MB fp16 scratch

__device__ __forceinline__ float tanh_fast(float x) {
    float r; asm("tanh.approx.f32 %0, %1;" : "=f"(r) : "f"(x)); return r;
}
__device__ __forceinline__ ull fma2(ull a, ull b, ull c) {
    ull d; asm("fma.rn.f32x2 %0, %1, %2, %3;" : "=l"(d) : "l"(a), "l"(b), "l"(c));
    return d;
}
__device__ __forceinline__ ull add2(ull a, ull b) {
    ull d; asm("add.rn.f32x2 %0, %1, %2;" : "=l"(d) : "l"(a), "l"(b));
    return d;
}
__device__ __forceinline__ ull pack2(float x, float y) {
    ull v; asm("mov.b64 %0, {%1, %2};" : "=l"(v) : "f"(x), "f"(y)); return v;
}
__device__ __forceinline__ float2 unpack2(ull v) {
    float2 f; asm("mov.b64 {%0, %1}, %2;" : "=f"(f.x), "=f"(f.y) : "l"(v)); return f;
}

// one LSTM timestep (compile-time ping-pong buffers)
#define STEP(XC, HR, HW)                                                      \
    do {                                                                      \
        ull a0 = pack2(fmaf((XC), wih, bsum), 0.f);                           \
        ull a1 = 0ull, a2 = 0ull, a3 = 0ull;                                  \
        _Pragma("unroll")                                                     \
        for (int i = 0; i < 4; i++) {                                         \
            ulonglong2 ha  = *(const ulonglong2*)((HR) + 8 * i);              \
            ulonglong2 hb2 = *(const ulonglong2*)((HR) + 8 * i + 4);          \
            a0 = fma2(w2[4 * i + 0], ha.x,  a0);                              \
            a1 = fma2(w2[4 * i + 1], ha.y,  a1);                              \
            a2 = fma2(w2[4 * i + 2], hb2.x, a2);                              \
            a3 = fma2(w2[4 * i + 3], hb2.y, a3);                              \
        }                                                                     \
        ull s = add2(add2(a0, a1), add2(a2, a3));                             \
        float2 sf = unpack2(s);                                               \
        float act = fmaf(tanh_fast(sf.x + sf.y), sa, sb);                     \
        float iv = __shfl_sync(0xffffffffu, act, base4);                      \
        float fv = __shfl_sync(0xffffffffu, act, base4 + 1);                  \
        float gv = __shfl_sync(0xffffffffu, act, base4 + 2);                  \
        c = fmaf(fv, c, iv * gv);                                             \
        float hres = act * tanh_fast(c);   /* act == o on writer lane */     \
        if (writer) (HW)[j] = hres;                                           \
        __syncthreads();                                                      \
        if (writer) *gout = __float2half_rn(hres);  /* in BAR wait window */  \
        gout += HID;                                                          \
    } while (0)

__global__ __launch_bounds__(NT, 1)
void lstm_rec(const float* __restrict__ x,
              const float* __restrict__ W_ih,
              const float* __restrict__ W_hh,
              const float* __restrict__ b_ih,
              const float* __restrict__ b_hh)
{
    __shared__ __align__(16) float hb[2][HID];

    const int tid  = threadIdx.x;
    const int wid  = tid >> 5;
    const int lane = tid & 31;
    const int b    = blockIdx.x;

    const int g   = lane & 3;                  // gate: 0=i 1=f 2=g 3=o
    const int j   = (wid << 3) + (lane >> 2);  // hidden unit
    const int row = (g << 5) + j;

    // sigmoid(z) = 0.5*tanh(z/2)+0.5 : fold the /2 into the weights
    const float scale = (g == 2) ? 1.0f : 0.5f;
    const float sa    = (g == 2) ? 1.0f : 0.5f;
    const float sb    = (g == 2) ? 0.0f : 0.5f;

    ull w2[16];
    #pragma unroll
    for (int k = 0; k < 16; k++) {
        float wa = W_hh[row * HID + 2 * k]     * scale;
        float wb = W_hh[row * HID + 2 * k + 1] * scale;
        w2[k] = pack2(wa, wb);
    }
    const float wih  = W_ih[row] * scale;
    const float bsum = (b_ih[row] + b_hh[row]) * scale;
    const int base4  = lane & ~3;
    const bool writer = (g == 3);              // owns o -> no o-shuffle

    __half* gout = h_dev + (size_t)b * TLEN * HID + j;
    const float* xb = x + (size_t)b * TLEN;
    float c = 0.f;

    if (tid < HID) hb[0][tid] = 0.f;
    __syncthreads();

    // register double-buffered x prefetch: block t's data loaded at block t-4
    float4 xn = __ldg((const float4*)xb);
    for (int t = 0; t < TLEN; t += 4) {
        float4 xq = xn;
        int tn = (t + 4 < TLEN) ? (t + 4) : t;          // clamp tail (L1 hit)
        xn = __ldg((const float4*)(xb + tn));
        STEP(xq.x, hb[0], hb[1]);
        STEP(xq.y, hb[1], hb[0]);
        STEP(xq.z, hb[0], hb[1]);
        STEP(xq.w, hb[1], hb[0]);
    }
}

// 256 rows per block staged through SMEM: global reads fully coalesced,
// 17-uint padded rows for conflict-free LDS (gcd(17,32)=1).
__global__ __launch_bounds__(256, 4)
void lin_head(const float* __restrict__ x,
              const float* __restrict__ W_lin,
              const float* __restrict__ b_lin,
              float* __restrict__ out)
{
    __shared__ uint hs[256 * 17];
    const int tid = threadIdx.x;
    const size_t base = (size_t)blockIdx.x * 256;        // first (b,t) row

    const uint4* src = (const uint4*)(h_dev + base * HID);
    #pragma unroll
    for (int i = 0; i < 4; i++) {
        int u = tid + i * 256;          // uint4 index 0..1023 (coalesced)
        uint4 v = src[u];
        int r = u >> 2, q = u & 3;
        uint* d = hs + r * 17 + q * 4;
        d[0] = v.x; d[1] = v.y; d[2] = v.z; d[3] = v.w;
    }
    __syncthreads();

    float w[32];
    #pragma unroll
    for (int k = 0; k < 8; k++) {
        float4 wv = __ldg((const float4*)W_lin + k);
        w[4*k] = wv.x; w[4*k+1] = wv.y; w[4*k+2] = wv.z; w[4*k+3] = wv.w;
    }

    const uint* hr = hs + tid * 17;
    float a0 = 0.f, a1 = 0.f, a2 = 0.f, a3 = 0.f;
    #pragma unroll
    for (int k = 0; k < 4; k++) {
        float2 f0 = __half22float2(*(const __half2*)&hr[4*k+0]);
        float2 f1 = __half22float2(*(const __half2*)&hr[4*k+1]);
        float2 f2 = __half22float2(*(const __half2*)&hr[4*k+2]);
        float2 f3 = __half22float2(*(const __half2*)&hr[4*k+3]);
        a0 = fmaf(f0.x, w[8*k+0], fmaf(f0.y, w[8*k+1], a0));
        a1 = fmaf(f1.x, w[8*k+2], fmaf(f1.y, w[8*k+3], a1));
        a2 = fmaf(f2.x, w[8*k+4], fmaf(f2.y, w[8*k+5], a2));
        a3 = fmaf(f3.x, w[8*k+6], fmaf(f3.y, w[8*k+7], a3));
    }
    const size_t idx = base + tid;
    out[idx] = x[idx] + __ldg(b_lin) + ((a0 + a1) + (a2 + a3));
}

extern "C" void kernel_launch(void* const* d_in, const int* in_sizes, int n_in,
                              void* d_out, int out_size) {
    lstm_rec<<<BATCH, NT>>>(
        (const float*)d_in[0],   // x
        (const float*)d_in[1],   // W_ih
        (const float*)d_in[2],   // W_hh
        (const float*)d_in[3],   // b_ih
        (const float*)d_in[4]);  // b_hh
    lin_head<<<(BATCH * TLEN) / 256, 256>>>(
        (const float*)d_in[0],   // x
        (const float*)d_in[5],   // W_lin
        (const float*)d_in[6],   // b_lin
        (float*)d_out);
}

// round 6
// speedup vs baseline: 2.2464x; 1.0263x over previous
#include <cuda_runtime.h>
#include <cuda_fp16.h>

// LSTM_8615704395881: B=64, T=16384, I=1, H=32, O=1.
// Kernel 1 (recurrent): 1 CTA/batch, 128 threads (4 homogeneous warps).
//   lane = 4*j_local + gate ; warp w owns hidden units [8w, 8w+8).
//   Per step: LDS h -> 32-MAC dot (f32x2, 4 chains; x/bias seed hoisted
//   to block top) -> MUFU.TANH act (0.5 folded into weights for sigmoid
//   gates) -> 3 shuffles (g,i,f order; writer lane g==3 owns o) ->
//   redundant cell update -> h STS (writer) -> barrier; fp16 STG in the
//   barrier-wait window. 8-step unroll, wrap-masked x prefetch.
// Kernel 2 (head): out = x + h_dev @ W_lin + b_lin.

#define BATCH 64
#define TLEN  16384
#define HID   32
#define NT    128

typedef unsigned long long ull;
typedef unsigned int uint;

__device__ __align__(16) __half h_dev[(size_t)BATCH * TLEN * HID];  // 64 MB fp16 scratch

__device__ __forceinline__ float tanh_fast(float x) {
    float r; asm("tanh.approx.f32 %0, %1;" : "=f"(r) : "f"(x)); return r;
}
__device__ __forceinline__ ull fma2(ull a, ull b, ull c) {
    ull d; asm("fma.rn.f32x2 %0, %1, %2, %3;" : "=l"(d) : "l"(a), "l"(b), "l"(c));
    return d;
}
__device__ __forceinline__ ull add2(ull a, ull b) {
    ull d; asm("add.rn.f32x2 %0, %1, %2;" : "=l"(d) : "l"(a), "l"(b));
    return d;
}
__device__ __forceinline__ ull pack2(float x, float y) {
    ull v; asm("mov.b64 %0, {%1, %2};" : "=l"(v) : "f"(x), "f"(y)); return v;
}
__device__ __forceinline__ float2 unpack2(ull v) {
    float2 f; asm("mov.b64 {%0, %1}, %2;" : "=f"(f.x), "=f"(f.y) : "l"(v)); return f;
}

// one LSTM timestep; X0 = prepacked (x*wih + bias, 0) seed
#define STEP(X0, HR, HW)                                                      \
    do {                                                                      \
        ull a0 = (X0);                                                        \
        ull a1 = 0ull, a2 = 0ull, a3 = 0ull;                                  \
        _Pragma("unroll")                                                     \
        for (int i = 0; i < 4; i++) {                                         \
            ulonglong2 ha  = *(const ulonglong2*)((HR) + 8 * i);              \
            ulonglong2 hb2 = *(const ulonglong2*)((HR) + 8 * i + 4);          \
            a0 = fma2(w2[4 * i + 0], ha.x,  a0);                              \
            a1 = fma2(w2[4 * i + 1], ha.y,  a1);                              \
            a2 = fma2(w2[4 * i + 2], hb2.x, a2);                              \
            a3 = fma2(w2[4 * i + 3], hb2.y, a3);                              \
        }                                                                     \
        ull s = add2(add2(a0, a1), add2(a2, a3));                             \
        float2 sf = unpack2(s);                                               \
        float act = fmaf(tanh_fast(sf.x + sf.y), sa, sb);                     \
        float gv = __shfl_sync(0xffffffffu, act, base4 + 2);                  \
        float iv = __shfl_sync(0xffffffffu, act, base4);                      \
        float fv = __shfl_sync(0xffffffffu, act, base4 + 1);                  \
        c = fmaf(fv, c, iv * gv);                                             \
        float hres = act * tanh_fast(c);   /* act == o on writer lane */      \
        if (writer) (HW)[j] = hres;                                           \
        __syncthreads();                                                      \
        if (writer) *gout = __float2half_rn(hres);  /* in BAR wait window */  \
        gout += HID;                                                          \
    } while (0)

__global__ __launch_bounds__(NT, 1)
void lstm_rec(const float* __restrict__ x,
              const float* __restrict__ W_ih,
              const float* __restrict__ W_hh,
              const float* __restrict__ b_ih,
              const float* __restrict__ b_hh)
{
    __shared__ __align__(128) float hb[2][HID];

    const int tid  = threadIdx.x;
    const int wid  = tid >> 5;
    const int lane = tid & 31;
    const int b    = blockIdx.x;

    const int g   = lane & 3;                  // gate: 0=i 1=f 2=g 3=o
    const int j   = (wid << 3) + (lane >> 2);  // hidden unit
    const int row = (g << 5) + j;

    // sigmoid(z) = 0.5*tanh(z/2)+0.5 : fold the /2 into the weights
    const float scale = (g == 2) ? 1.0f : 0.5f;
    const float sa    = (g == 2) ? 1.0f : 0.5f;
    const float sb    = (g == 2) ? 0.0f : 0.5f;

    ull w2[16];
    #pragma unroll
    for (int k = 0; k < 16; k++) {
        float wa = W_hh[row * HID + 2 * k]     * scale;
        float wb = W_hh[row * HID + 2 * k + 1] * scale;
        w2[k] = pack2(wa, wb);
    }
    const float wih  = W_ih[row] * scale;
    const float bsum = (b_ih[row] + b_hh[row]) * scale;
    const int base4  = lane & ~3;
    const bool writer = (g == 3);              // owns o -> no o-shuffle

    __half* gout = h_dev + (size_t)b * TLEN * HID + j;
    const float* xb = x + (size_t)b * TLEN;
    float c = 0.f;

    if (tid < HID) hb[0][tid] = 0.f;
    __syncthreads();

    // prefetch one 8-step block ahead (wrap-masked, no compare/select)
    float4 xn0 = __ldg((const float4*)xb);
    float4 xn1 = __ldg((const float4*)(xb + 4));
    for (int t = 0; t < TLEN; t += 8) {
        const float4 xa = xn0, xc4 = xn1;
        const int tn = (t + 8) & (TLEN - 1);
        xn0 = __ldg((const float4*)(xb + tn));
        xn1 = __ldg((const float4*)(xb + tn + 4));

        // hoist all x/bias seeds off the per-step critical path
        ull s0 = pack2(fmaf(xa.x,  wih, bsum), 0.f);
        ull s1 = pack2(fmaf(xa.y,  wih, bsum), 0.f);
        ull s2 = pack2(fmaf(xa.z,  wih, bsum), 0.f);
        ull s3 = pack2(fmaf(xa.w,  wih, bsum), 0.f);
        ull s4 = pack2(fmaf(xc4.x, wih, bsum), 0.f);
        ull s5 = pack2(fmaf(xc4.y, wih, bsum), 0.f);
        ull s6 = pack2(fmaf(xc4.z, wih, bsum), 0.f);
        ull s7 = pack2(fmaf(xc4.w, wih, bsum), 0.f);

        STEP(s0, hb[0], hb[1]);
        STEP(s1, hb[1], hb[0]);
        STEP(s2, hb[0], hb[1]);
        STEP(s3, hb[1], hb[0]);
        STEP(s4, hb[0], hb[1]);
        STEP(s5, hb[1], hb[0]);
        STEP(s6, hb[0], hb[1]);
        STEP(s7, hb[1], hb[0]);
    }
}

// 256 rows per block staged through SMEM: global reads fully coalesced,
// 17-uint padded rows for conflict-free LDS (gcd(17,32)=1).
__global__ __launch_bounds__(256, 4)
void lin_head(const float* __restrict__ x,
              const float* __restrict__ W_lin,
              const float* __restrict__ b_lin,
              float* __restrict__ out)
{
    __shared__ uint hs[256 * 17];
    const int tid = threadIdx.x;
    const size_t base = (size_t)blockIdx.x * 256;        // first (b,t) row

    const uint4* src = (const uint4*)(h_dev + base * HID);
    #pragma unroll
    for (int i = 0; i < 4; i++) {
        int u = tid + i * 256;          // uint4 index 0..1023 (coalesced)
        uint4 v = src[u];
        int r = u >> 2, q = u & 3;
        uint* d = hs + r * 17 + q * 4;
        d[0] = v.x; d[1] = v.y; d[2] = v.z; d[3] = v.w;
    }
    __syncthreads();

    float w[32];
    #pragma unroll
    for (int k = 0; k < 8; k++) {
        float4 wv = __ldg((const float4*)W_lin + k);
        w[4*k] = wv.x; w[4*k+1] = wv.y; w[4*k+2] = wv.z; w[4*k+3] = wv.w;
    }

    const uint* hr = hs + tid * 17;
    float a0 = 0.f, a1 = 0.f, a2 = 0.f, a3 = 0.f;
    #pragma unroll
    for (int k = 0; k < 4; k++) {
        float2 f0 = __half22float2(*(const __half2*)&hr[4*k+0]);
        float2 f1 = __half22float2(*(const __half2*)&hr[4*k+1]);
        float2 f2 = __half22float2(*(const __half2*)&hr[4*k+2]);
        float2 f3 = __half22float2(*(const __half2*)&hr[4*k+3]);
        a0 = fmaf(f0.x, w[8*k+0], fmaf(f0.y, w[8*k+1], a0));
        a1 = fmaf(f1.x, w[8*k+2], fmaf(f1.y, w[8*k+3], a1));
        a2 = fmaf(f2.x, w[8*k+4], fmaf(f2.y, w[8*k+5], a2));
        a3 = fmaf(f3.x, w[8*k+6], fmaf(f3.y, w[8*k+7], a3));
    }
    const size_t idx = base + tid;
    out[idx] = x[idx] + __ldg(b_lin) + ((a0 + a1) + (a2 + a3));
}

extern "C" void kernel_launch(void* const* d_in, const int* in_sizes, int n_in,
                              void* d_out, int out_size) {
    lstm_rec<<<BATCH, NT>>>(
        (const float*)d_in[0],   // x
        (const float*)d_in[1],   // W_ih
        (const float*)d_in[2],   // W_hh
        (const float*)d_in[3],   // b_ih
        (const float*)d_in[4]);  // b_hh
    lin_head<<<(BATCH * TLEN) / 256, 256>>>(
        (const float*)d_in[0],   // x
        (const float*)d_in[5],   // W_lin
        (const float*)d_in[6],   // b_lin
        (float*)d_out);
}